// round 2
// baseline (speedup 1.0000x reference)
#include <cuda_runtime.h>
#include <math.h>

#define NCLS 21

// ---------------- scratch (static device globals; no allocation) ----------------
__device__ float g_h1[64 * 256 * 256];   // conv1 out
__device__ float g_h2[128 * 128 * 128];  // conv2 out
__device__ float g_h3[256 * 64 * 64];    // conv3 out
__device__ float g_h4[256 * 32 * 32];    // ex out
__device__ float g_part[8 * 25 * 1024];  // head conv split-K partials
__device__ float g_locs[1024 * 4];
__device__ float g_confs[1024 * NCLS];
__device__ float g_scores[1024];
__device__ int g_labels[1024];
__device__ int g_order[1024];
__device__ float4 g_sbox[1024];
__device__ float g_sscore[1024];
__device__ unsigned g_validmask[32];
__device__ unsigned g_sup[1024 * 32];
__device__ unsigned g_keepmask[32];

// ---------------- generic 3x3 conv, stride 2, SAME padding ----------------
// JAX SAME for even input, stride 2: pad_lo = 0, pad_hi = 1 (out = in/2).
// Block: 16x16 output tile, COUTS output channels.
// Accuracy: per-channel 9-term FMA window sum, then Kahan-compensated add into
// the cross-channel accumulator (keeps total error at ~1-2 ulp of exact).
template <int CIN, int WCH, int STRIDE, int COUTS>
__device__ __forceinline__ void conv_body(const float* __restrict__ in,
                                          const float* __restrict__ wgt,
                                          const float* __restrict__ bias,
                                          float* __restrict__ out, int Hin,
                                          int Win, int Hout, int Wout,
                                          int Cout) {
  constexpr int TILE = 16;
  constexpr int IN_T = TILE * STRIDE + 2;
  __shared__ float s_in[IN_T][IN_T + 2];
  __shared__ __align__(16) float s_w[WCH * 9 * COUTS];

  const int tx = threadIdx.x, ty = threadIdx.y;
  const int t = ty * 16 + tx;
  const int ow0 = blockIdx.x * TILE, oh0 = blockIdx.y * TILE;
  const int co0 = blockIdx.z * COUTS;

  float acc[COUTS], cmp[COUTS];
#pragma unroll
  for (int i = 0; i < COUTS; i++) { acc[i] = 0.f; cmp[i] = 0.f; }

  for (int c0 = 0; c0 < CIN; c0 += WCH) {
    __syncthreads();
    // stage weight chunk: layout s_w[(cc*9+k)*COUTS + co]
    for (int idx = t; idx < COUTS * WCH * 9; idx += 256) {
      int co = idx / (WCH * 9);
      int rem = idx - co * (WCH * 9);
      int cc = rem / 9, k = rem - cc * 9;
      s_w[(cc * 9 + k) * COUTS + co] =
          wgt[(size_t)(co0 + co) * CIN * 9 + (size_t)(c0 + cc) * 9 + k];
    }
    __syncthreads();

    for (int cc = 0; cc < WCH; ++cc) {
      const int c = c0 + cc;
      // stage input tile for channel c
      for (int idx = t; idx < IN_T * IN_T; idx += 256) {
        int r = idx / IN_T, col = idx - r * IN_T;
        int ih = oh0 * STRIDE + r;
        int iw = ow0 * STRIDE + col;
        float v = 0.f;
        if ((unsigned)ih < (unsigned)Hin && (unsigned)iw < (unsigned)Win)
          v = in[(size_t)c * Hin * Win + (size_t)ih * Win + iw];
        s_in[r][col] = v;
      }
      __syncthreads();

      float wsum[COUTS];
#pragma unroll
      for (int i = 0; i < COUTS; i++) wsum[i] = 0.f;
#pragma unroll
      for (int kh = 0; kh < 3; ++kh)
#pragma unroll
        for (int kw = 0; kw < 3; ++kw) {
          float xv = s_in[ty * STRIDE + kh][tx * STRIDE + kw];
          const float4* wp =
              (const float4*)&s_w[(cc * 9 + kh * 3 + kw) * COUTS];
#pragma unroll
          for (int q = 0; q < COUTS / 4; ++q) {
            float4 w4 = wp[q];
            wsum[q * 4 + 0] = fmaf(xv, w4.x, wsum[q * 4 + 0]);
            wsum[q * 4 + 1] = fmaf(xv, w4.y, wsum[q * 4 + 1]);
            wsum[q * 4 + 2] = fmaf(xv, w4.z, wsum[q * 4 + 2]);
            wsum[q * 4 + 3] = fmaf(xv, w4.w, wsum[q * 4 + 3]);
          }
        }
      // Kahan-compensated accumulate across channels
#pragma unroll
      for (int i = 0; i < COUTS; i++) {
        float y = wsum[i] - cmp[i];
        float tt = acc[i] + y;
        cmp[i] = (tt - acc[i]) - y;
        acc[i] = tt;
      }
      __syncthreads();
    }
  }

  const int oh = oh0 + ty, ow = ow0 + tx;
#pragma unroll
  for (int i = 0; i < COUTS; i++) {
    float v = acc[i] + bias[co0 + i];
    v = fmaxf(v, 0.f);  // all backbone convs use relu
    out[(size_t)(co0 + i) * Hout * Wout + (size_t)oh * Wout + ow] = v;
  }
}

__global__ void k_conv1(const float* x, const float* w, const float* b) {
  conv_body<3, 3, 2, 4>(x, w, b, g_h1, 512, 512, 256, 256, 64);
}
__global__ void k_conv2(const float* w, const float* b) {
  conv_body<64, 64, 2, 8>(g_h1, w, b, g_h2, 256, 256, 128, 128, 128);
}
__global__ void k_conv3(const float* w, const float* b) {
  conv_body<128, 128, 2, 8>(g_h2, w, b, g_h3, 128, 128, 64, 64, 256);
}
__global__ void k_ex(const float* w, const float* b) {
  conv_body<256, 128, 2, 8>(g_h3, w, b, g_h4, 64, 64, 32, 32, 256);
}

// ---------------- head convs (reg 4ch + cls 21ch), stride1 pad1, split-K -------
// grid: (split 0..7, cout 0..24). Each block: 32 input channels, all 1024 px.
// Kahan-compensated per-split partial; splits summed in double in k_prep.
__global__ void k_head(const float* __restrict__ reg_w,
                       const float* __restrict__ cls_w) {
  const int split = blockIdx.x, co = blockIdx.y;
  const float* w = (co < 4) ? (reg_w + (size_t)co * 256 * 9)
                            : (cls_w + (size_t)(co - 4) * 256 * 9);
  __shared__ float s_in[34][35];
  __shared__ float s_w[9];
  const int t = threadIdx.x;
  float acc[4] = {0.f, 0.f, 0.f, 0.f};
  float cmp[4] = {0.f, 0.f, 0.f, 0.f};

  for (int cc = 0; cc < 32; ++cc) {
    const int c = split * 32 + cc;
    __syncthreads();
    if (t < 9) s_w[t] = w[c * 9 + t];
    for (int idx = t; idx < 34 * 34; idx += 256) {
      int r = idx / 34, col = idx - r * 34;
      int ih = r - 1, iw = col - 1;
      float v = 0.f;
      if ((unsigned)ih < 32u && (unsigned)iw < 32u)
        v = g_h4[(size_t)c * 1024 + ih * 32 + iw];
      s_in[r][col] = v;
    }
    __syncthreads();
#pragma unroll
    for (int px = 0; px < 4; ++px) {
      int p = t + px * 256;
      int oh = p >> 5, ow = p & 31;
      float a = 0.f;
#pragma unroll
      for (int kh = 0; kh < 3; ++kh)
#pragma unroll
        for (int kw = 0; kw < 3; ++kw)
          a = fmaf(s_in[oh + kh][ow + kw], s_w[kh * 3 + kw], a);
      float y = a - cmp[px];
      float tt = acc[px] + y;
      cmp[px] = (tt - acc[px]) - y;
      acc[px] = tt;
    }
  }
#pragma unroll
  for (int px = 0; px < 4; ++px)
    g_part[(size_t)(split * 25 + co) * 1024 + t + px * 256] = acc[px];
}

// ---------------- reduce partials (double) + transpose + softmax (double) ------
__global__ void k_prep(const float* __restrict__ reg_b,
                       const float* __restrict__ cls_b) {
  const int a = blockIdx.x * 256 + threadIdx.x;  // anchor 0..1023
  // locs
#pragma unroll
  for (int j = 0; j < 4; ++j) {
    double s = 0.0;
    for (int sp = 0; sp < 8; ++sp)
      s += (double)g_part[(size_t)(sp * 25 + j) * 1024 + a];
    g_locs[a * 4 + j] = (float)(s + (double)reg_b[j]);
  }
  float conf[NCLS];
  for (int c = 0; c < NCLS; ++c) {
    double s = 0.0;
    for (int sp = 0; sp < 8; ++sp)
      s += (double)g_part[(size_t)(sp * 25 + 4 + c) * 1024 + a];
    conf[c] = (float)(s + (double)cls_b[c]);
    g_confs[a * NCLS + c] = conf[c];
  }
  float m = conf[0];
  int lab = 0;
  for (int c = 1; c < NCLS; ++c)
    if (conf[c] > m) { m = conf[c]; lab = c; }
  double sum = 0.0;
  for (int c = 0; c < NCLS; ++c) sum += exp((double)conf[c] - (double)m);
  g_scores[a] = (float)(1.0 / sum);  // max softmax prob
  g_labels[a] = lab;
}

// ---------------- stable bitonic sort by descending score ----------------
__global__ void k_sort() {
  __shared__ float s[1024];
  __shared__ int si[1024];
  const int t = threadIdx.x;
  s[t] = g_scores[t];
  si[t] = t;
  __syncthreads();
  for (int k = 2; k <= 1024; k <<= 1) {
    for (int j = k >> 1; j > 0; j >>= 1) {
      int ixj = t ^ j;
      if (ixj > t) {
        float sa = s[t], sb = s[ixj];
        int ia = si[t], ib = si[ixj];
        // "a before b" = higher score, ties -> lower original index (stable)
        bool aFirst = (sa > sb) || (sa == sb && ia < ib);
        bool dirUp = ((t & k) == 0);
        if (dirUp ? !aFirst : aFirst) {
          s[t] = sb; s[ixj] = sa;
          si[t] = ib; si[ixj] = ia;
        }
      }
      __syncthreads();
    }
  }
  const int idx = si[t];
  g_order[t] = idx;
  g_sscore[t] = s[t];
  g_sbox[t] = make_float4(g_locs[idx * 4 + 0], g_locs[idx * 4 + 1],
                          g_locs[idx * 4 + 2], g_locs[idx * 4 + 3]);
  unsigned vb = __ballot_sync(0xffffffffu, s[t] > 0.04f);
  if ((t & 31) == 0) g_validmask[t >> 5] = vb;
}

// ---------------- pairwise IoU suppression bitmask (double precision) ----------
__global__ void k_iou() {
  const int i = blockIdx.x, j = threadIdx.x;
  float4 bi = g_sbox[i];
  float4 bj = g_sbox[j];
  double ai = ((double)bi.z - (double)bi.x) * ((double)bi.w - (double)bi.y);
  double aj = ((double)bj.z - (double)bj.x) * ((double)bj.w - (double)bj.y);
  double ltx = fmax((double)bi.x, (double)bj.x);
  double lty = fmax((double)bi.y, (double)bj.y);
  double rbx = fmin((double)bi.z, (double)bj.z);
  double rby = fmin((double)bi.w, (double)bj.w);
  double inter = fmax(rbx - ltx, 0.0) * fmax(rby - lty, 0.0);
  double uni = ai + aj - inter;
  double iou = inter / (uni + 1e-9);
  unsigned m = __ballot_sync(0xffffffffu, iou > 0.5);
  if ((j & 31) == 0) g_sup[i * 32 + (j >> 5)] = m;
}

// ---------------- sequential greedy NMS on bitmask, single warp ----------------
__global__ void k_nms() {
  const int lane = threadIdx.x;  // 32 threads
  unsigned kw = 0;
  const unsigned validw = g_validmask[lane];
  const int CH = 8;
  unsigned buf[CH], nbuf[CH];
#pragma unroll
  for (int q = 0; q < CH; ++q) buf[q] = g_sup[q * 32 + lane];
  for (int c = 0; c < 1024 / CH; ++c) {
    if (c + 1 < 1024 / CH) {
#pragma unroll
      for (int q = 0; q < CH; ++q)
        nbuf[q] = g_sup[((c + 1) * CH + q) * 32 + lane];
    }
#pragma unroll
    for (int q = 0; q < CH; ++q) {
      int i = c * CH + q;
      bool sup = __any_sync(0xffffffffu, (buf[q] & kw) != 0u);
      unsigned vbit =
          (__shfl_sync(0xffffffffu, validw, i >> 5) >> (i & 31)) & 1u;
      if (!sup && vbit && lane == (i >> 5)) kw |= (1u << (i & 31));
    }
#pragma unroll
    for (int q = 0; q < CH; ++q) buf[q] = nbuf[q];
  }
  g_keepmask[lane] = kw;
}

// ---------------- masked gather to output ----------------
// layout (float32): boxes[1024*4] | labels[1024] | scores[1024] | confs[1024*21]
__global__ void k_out(float* __restrict__ out) {
  const int p = blockIdx.x * 256 + threadIdx.x;  // 0..1023
  const bool keep = (g_keepmask[p >> 5] >> (p & 31)) & 1u;
  const int idx = g_order[p];
  float4 b = g_sbox[p];
  out[p * 4 + 0] = keep ? b.x : -1.0f;
  out[p * 4 + 1] = keep ? b.y : -1.0f;
  out[p * 4 + 2] = keep ? b.z : -1.0f;
  out[p * 4 + 3] = keep ? b.w : -1.0f;
  out[4096 + p] = keep ? (float)g_labels[idx] : 0.0f;
  out[5120 + p] = keep ? g_sscore[p] : -1.0f;
  for (int c = 0; c < NCLS; ++c)
    out[6144 + p * NCLS + c] = keep ? g_confs[idx * NCLS + c] : -1.0f;
}

// ---------------- launch ----------------
extern "C" void kernel_launch(void* const* d_in, const int* in_sizes, int n_in,
                              void* d_out, int out_size) {
  const float* x = (const float*)d_in[0];
  const float* bb_w1 = (const float*)d_in[1];
  const float* bb_b1 = (const float*)d_in[2];
  const float* bb_w2 = (const float*)d_in[3];
  const float* bb_b2 = (const float*)d_in[4];
  const float* bb_w3 = (const float*)d_in[5];
  const float* bb_b3 = (const float*)d_in[6];
  const float* ex_w = (const float*)d_in[7];
  const float* ex_b = (const float*)d_in[8];
  const float* reg_w = (const float*)d_in[9];
  const float* reg_b = (const float*)d_in[10];
  const float* cls_w = (const float*)d_in[11];
  const float* cls_b = (const float*)d_in[12];

  // only batch element 7 affects the output
  const float* x7 = x + (size_t)7 * 3 * 512 * 512;

  k_conv1<<<dim3(16, 16, 16), dim3(16, 16)>>>(x7, bb_w1, bb_b1);
  k_conv2<<<dim3(8, 8, 16), dim3(16, 16)>>>(bb_w2, bb_b2);
  k_conv3<<<dim3(4, 4, 32), dim3(16, 16)>>>(bb_w3, bb_b3);
  k_ex<<<dim3(2, 2, 32), dim3(16, 16)>>>(ex_w, ex_b);
  k_head<<<dim3(8, 25), 256>>>(reg_w, cls_w);
  k_prep<<<4, 256>>>(reg_b, cls_b);
  k_sort<<<1, 1024>>>();
  k_iou<<<1024, 1024>>>();
  k_nms<<<1, 32>>>();
  k_out<<<4, 256>>>((float*)d_out);
}

// round 4
// speedup vs baseline: 1.7515x; 1.7515x over previous
#include <cuda_runtime.h>
#include <math.h>

#define NCLS 21

// ---------------- scratch (static device globals; no allocation) ----------------
__device__ float g_h1[64 * 256 * 256];   // conv1 out
__device__ float g_h2[128 * 128 * 128];  // conv2 out
__device__ float g_h3[256 * 64 * 64];    // conv3 out
__device__ float g_h4[256 * 32 * 32];    // ex out
__device__ float g_part[8 * 25 * 1024];  // head conv split-K partials
__device__ float g_locs[1024 * 4];
__device__ float g_confs[1024 * NCLS];
__device__ float g_scores[1024];
__device__ int g_labels[1024];
__device__ int g_order[1024];
__device__ float4 g_sbox[1024];
__device__ float g_sscore[1024];
__device__ unsigned g_validmask[32];
__device__ unsigned g_sup[1024 * 32];
__device__ unsigned g_keepmask[32];

// ---------------- 3x3 conv, stride 2, SAME padding ----------------
// JAX SAME, even input, stride 2: pad_lo=0, pad_hi=1 (out = in/2).
// 16x16 output tile, COUTS output channels per block, 256 threads.
// NCH input channels staged per sync-pair; next group's loads prefetched into
// registers (fully unrolled -> high MLP) while current group computes.
// Numerics IDENTICAL to the R2-passing kernel: per input channel, a 9-term
// FMA chain (wsum), then Kahan-compensated fold into the accumulator.
template <int CIN, int WCH, int NCH, int STRIDE, int COUTS>
__device__ __forceinline__ void conv_body(const float* __restrict__ in,
                                          const float* __restrict__ wgt,
                                          const float* __restrict__ bias,
                                          float* __restrict__ out, int Hin,
                                          int Win, int Hout, int Wout) {
  constexpr int TILE = 16;
  constexpr int IN_T = TILE * STRIDE + 2;
  constexpr int ROWP = IN_T + 2;
  constexpr int ELEMS = NCH * IN_T * IN_T;
  constexpr int LD = (ELEMS + 255) / 256;
  constexpr int G = WCH / NCH;
  constexpr int NW = WCH * 9 * COUTS;
  constexpr int WLD = (NW + 255) / 256;

  __shared__ float s_in[NCH * IN_T * ROWP];
  __shared__ __align__(16) float s_w[NW];

  const int t = threadIdx.x;
  const int tx = t & 15, ty = t >> 4;
  const int ow0 = blockIdx.x * TILE, oh0 = blockIdx.y * TILE;
  const int co0 = blockIdx.z * COUTS;
  const int HW = Hin * Win;

  // per-thread load descriptors (same for every channel group)
  int goff[LD], soff[LD];
#pragma unroll
  for (int i = 0; i < LD; ++i) {
    int idx = t + i * 256;
    int ch = idx / (IN_T * IN_T);
    int rem = idx - ch * (IN_T * IN_T);
    int r = rem / IN_T, c = rem - r * IN_T;
    int ih = oh0 * STRIDE + r, iw = ow0 * STRIDE + c;
    bool ok = (idx < ELEMS) && ((unsigned)ih < (unsigned)Hin) &&
              ((unsigned)iw < (unsigned)Win);
    goff[i] = ok ? (ch * HW + ih * Win + iw) : -1;
    soff[i] = (ch * IN_T + r) * ROWP + c;
  }

  float acc[COUTS], cmp[COUTS];
#pragma unroll
  for (int i = 0; i < COUTS; i++) { acc[i] = 0.f; cmp[i] = 0.f; }

  for (int c0 = 0; c0 < CIN; c0 += WCH) {
    __syncthreads();  // previous chunk compute done; smem reusable
    // stage weight chunk: s_w[(ccg*9+k)*COUTS + co]
#pragma unroll
    for (int i = 0; i < WLD; ++i) {
      int idx = t + i * 256;
      if (idx < NW) {
        int co = idx / (WCH * 9);
        int rem = idx - co * (WCH * 9);
        int ccg = rem / 9, k = rem - ccg * 9;
        s_w[(ccg * 9 + k) * COUTS + co] =
            wgt[(size_t)(co0 + co) * CIN * 9 + (size_t)(c0 + ccg) * 9 + k];
      }
    }
    // prefetch group 0
    float rbuf[LD];
    {
      const float* inb = in + (size_t)c0 * HW;
#pragma unroll
      for (int i = 0; i < LD; ++i)
        rbuf[i] = (goff[i] >= 0) ? inb[goff[i]] : 0.f;
    }
    for (int g = 0; g < G; ++g) {
      __syncthreads();  // compute(g-1) done before overwriting s_in
#pragma unroll
      for (int i = 0; i < LD; ++i)
        if (t + i * 256 < ELEMS) s_in[soff[i]] = rbuf[i];
      if (g + 1 < G) {  // prefetch next group (overlaps with compute below)
        const float* inb = in + (size_t)(c0 + (g + 1) * NCH) * HW;
#pragma unroll
        for (int i = 0; i < LD; ++i)
          rbuf[i] = (goff[i] >= 0) ? inb[goff[i]] : 0.f;
      }
      __syncthreads();  // staging (weights + input) visible

#pragma unroll
      for (int cc = 0; cc < NCH; ++cc) {
        float wsum[COUTS];
#pragma unroll
        for (int i = 0; i < COUTS; ++i) wsum[i] = 0.f;
#pragma unroll
        for (int kh = 0; kh < 3; ++kh)
#pragma unroll
          for (int kw = 0; kw < 3; ++kw) {
            float xv = s_in[(cc * IN_T + ty * STRIDE + kh) * ROWP +
                            tx * STRIDE + kw];
            const float4* wp = (const float4*)&s_w[((g * NCH + cc) * 9 +
                                                    kh * 3 + kw) * COUTS];
#pragma unroll
            for (int q = 0; q < COUTS / 4; ++q) {
              float4 w4 = wp[q];
              wsum[q * 4 + 0] = fmaf(xv, w4.x, wsum[q * 4 + 0]);
              wsum[q * 4 + 1] = fmaf(xv, w4.y, wsum[q * 4 + 1]);
              wsum[q * 4 + 2] = fmaf(xv, w4.z, wsum[q * 4 + 2]);
              wsum[q * 4 + 3] = fmaf(xv, w4.w, wsum[q * 4 + 3]);
            }
          }
        // Kahan fold per channel (matches R2-passing numerics exactly)
#pragma unroll
        for (int i = 0; i < COUTS; ++i) {
          float y = wsum[i] - cmp[i];
          float tt = acc[i] + y;
          cmp[i] = (tt - acc[i]) - y;
          acc[i] = tt;
        }
      }
    }
  }

  const int oh = oh0 + ty, ow = ow0 + tx;
#pragma unroll
  for (int i = 0; i < COUTS; i++) {
    float v = acc[i] + bias[co0 + i];
    v = fmaxf(v, 0.f);
    out[(size_t)(co0 + i) * Hout * Wout + (size_t)oh * Wout + ow] = v;
  }
}

__global__ void __launch_bounds__(256) k_conv1(const float* x, const float* w,
                                               const float* b) {
  conv_body<3, 3, 3, 2, 4>(x, w, b, g_h1, 512, 512, 256, 256);
}
__global__ void __launch_bounds__(256) k_conv2(const float* w, const float* b) {
  conv_body<64, 64, 4, 2, 8>(g_h1, w, b, g_h2, 256, 256, 128, 128);
}
__global__ void __launch_bounds__(256) k_conv3(const float* w, const float* b) {
  conv_body<128, 64, 4, 2, 8>(g_h2, w, b, g_h3, 128, 128, 64, 64);
}
__global__ void __launch_bounds__(256) k_ex(const float* w, const float* b) {
  conv_body<256, 64, 4, 2, 8>(g_h3, w, b, g_h4, 64, 64, 32, 32);
}

// ---------------- head convs (reg 4ch + cls 21ch), stride1 pad1, split-K -------
// grid: (split 0..7, cout 0..24). Block: 32 input channels, all 1024 px.
// Batched 4 channels per sync-pair with register prefetch.
// Numerics identical to R2: per-channel 9-term chain + Kahan fold.
__global__ void __launch_bounds__(256) k_head(const float* __restrict__ reg_w,
                                              const float* __restrict__ cls_w) {
  constexpr int IN_T = 34, ROWP = 35, NCH = 4;
  constexpr int ELEMS = NCH * IN_T * IN_T;
  constexpr int LD = (ELEMS + 255) / 256;
  const int split = blockIdx.x, co = blockIdx.y;
  const float* w = (co < 4) ? (reg_w + (size_t)co * 256 * 9)
                            : (cls_w + (size_t)(co - 4) * 256 * 9);
  __shared__ float s_in[NCH * IN_T * ROWP];
  __shared__ float s_w[32 * 9];
  const int t = threadIdx.x;

  int goff[LD], soff[LD];
#pragma unroll
  for (int i = 0; i < LD; ++i) {
    int idx = t + i * 256;
    int ch = idx / (IN_T * IN_T);
    int rem = idx - ch * (IN_T * IN_T);
    int r = rem / IN_T, c = rem - r * IN_T;
    int ih = r - 1, iw = c - 1;
    bool ok = (idx < ELEMS) && ((unsigned)ih < 32u) && ((unsigned)iw < 32u);
    goff[i] = ok ? (ch * 1024 + ih * 32 + iw) : -1;
    soff[i] = (ch * IN_T + r) * ROWP + c;
  }
  // FIX (R3 bug): 32*9 = 288 > 256 threads -> must loop, not single guard
  for (int idx = t; idx < 32 * 9; idx += 256)
    s_w[idx] = w[(size_t)(split * 32 + idx / 9) * 9 + (idx % 9)];

  float acc[4] = {0.f, 0.f, 0.f, 0.f};
  float cmp[4] = {0.f, 0.f, 0.f, 0.f};

  float rbuf[LD];
  {
    const float* inb = g_h4 + (size_t)split * 32 * 1024;
#pragma unroll
    for (int i = 0; i < LD; ++i) rbuf[i] = (goff[i] >= 0) ? inb[goff[i]] : 0.f;
  }
  for (int g = 0; g < 8; ++g) {
    __syncthreads();
#pragma unroll
    for (int i = 0; i < LD; ++i)
      if (t + i * 256 < ELEMS) s_in[soff[i]] = rbuf[i];
    if (g + 1 < 8) {
      const float* inb = g_h4 + (size_t)(split * 32 + (g + 1) * NCH) * 1024;
#pragma unroll
      for (int i = 0; i < LD; ++i)
        rbuf[i] = (goff[i] >= 0) ? inb[goff[i]] : 0.f;
    }
    __syncthreads();

#pragma unroll
    for (int cc = 0; cc < NCH; ++cc) {
      float wr[9];
#pragma unroll
      for (int k = 0; k < 9; ++k) wr[k] = s_w[(g * NCH + cc) * 9 + k];
#pragma unroll
      for (int px = 0; px < 4; ++px) {
        int p = t + px * 256;
        int oh = p >> 5, ow = p & 31;
        float a = 0.f;
#pragma unroll
        for (int kh = 0; kh < 3; ++kh)
#pragma unroll
          for (int kw = 0; kw < 3; ++kw)
            a = fmaf(s_in[(cc * IN_T + oh + kh) * ROWP + ow + kw],
                     wr[kh * 3 + kw], a);
        float y = a - cmp[px];
        float tt = acc[px] + y;
        cmp[px] = (tt - acc[px]) - y;
        acc[px] = tt;
      }
    }
  }
#pragma unroll
  for (int px = 0; px < 4; ++px)
    g_part[(size_t)(split * 25 + co) * 1024 + t + px * 256] = acc[px];
}

// ---------------- reduce partials (double) + transpose + softmax (double) ------
__global__ void k_prep(const float* __restrict__ reg_b,
                       const float* __restrict__ cls_b) {
  const int a = blockIdx.x * 256 + threadIdx.x;  // anchor 0..1023
#pragma unroll
  for (int j = 0; j < 4; ++j) {
    double s = 0.0;
    for (int sp = 0; sp < 8; ++sp)
      s += (double)g_part[(size_t)(sp * 25 + j) * 1024 + a];
    g_locs[a * 4 + j] = (float)(s + (double)reg_b[j]);
  }
  float conf[NCLS];
  for (int c = 0; c < NCLS; ++c) {
    double s = 0.0;
    for (int sp = 0; sp < 8; ++sp)
      s += (double)g_part[(size_t)(sp * 25 + 4 + c) * 1024 + a];
    conf[c] = (float)(s + (double)cls_b[c]);
    g_confs[a * NCLS + c] = conf[c];
  }
  float m = conf[0];
  int lab = 0;
  for (int c = 1; c < NCLS; ++c)
    if (conf[c] > m) { m = conf[c]; lab = c; }
  double sum = 0.0;
  for (int c = 0; c < NCLS; ++c) sum += exp((double)conf[c] - (double)m);
  g_scores[a] = (float)(1.0 / sum);  // max softmax prob
  g_labels[a] = lab;
}

// ---------------- stable bitonic sort by descending score ----------------
__global__ void k_sort() {
  __shared__ float s[1024];
  __shared__ int si[1024];
  const int t = threadIdx.x;
  s[t] = g_scores[t];
  si[t] = t;
  __syncthreads();
  for (int k = 2; k <= 1024; k <<= 1) {
    for (int j = k >> 1; j > 0; j >>= 1) {
      int ixj = t ^ j;
      if (ixj > t) {
        float sa = s[t], sb = s[ixj];
        int ia = si[t], ib = si[ixj];
        bool aFirst = (sa > sb) || (sa == sb && ia < ib);  // stable desc
        bool dirUp = ((t & k) == 0);
        if (dirUp ? !aFirst : aFirst) {
          s[t] = sb; s[ixj] = sa;
          si[t] = ib; si[ixj] = ia;
        }
      }
      __syncthreads();
    }
  }
  const int idx = si[t];
  g_order[t] = idx;
  g_sscore[t] = s[t];
  g_sbox[t] = make_float4(g_locs[idx * 4 + 0], g_locs[idx * 4 + 1],
                          g_locs[idx * 4 + 2], g_locs[idx * 4 + 3]);
  unsigned vb = __ballot_sync(0xffffffffu, s[t] > 0.04f);
  if ((t & 31) == 0) g_validmask[t >> 5] = vb;
}

// ---------------- pairwise IoU suppression bitmask (double precision) ----------
__global__ void k_iou() {
  const int i = blockIdx.x, j = threadIdx.x;
  float4 bi = g_sbox[i];
  float4 bj = g_sbox[j];
  double ai = ((double)bi.z - (double)bi.x) * ((double)bi.w - (double)bi.y);
  double aj = ((double)bj.z - (double)bj.x) * ((double)bj.w - (double)bj.y);
  double ltx = fmax((double)bi.x, (double)bj.x);
  double lty = fmax((double)bi.y, (double)bj.y);
  double rbx = fmin((double)bi.z, (double)bj.z);
  double rby = fmin((double)bi.w, (double)bj.w);
  double inter = fmax(rbx - ltx, 0.0) * fmax(rby - lty, 0.0);
  double uni = ai + aj - inter;
  double iou = inter / (uni + 1e-9);
  unsigned m = __ballot_sync(0xffffffffu, iou > 0.5);
  if ((j & 31) == 0) g_sup[i * 32 + (j >> 5)] = m;
}

// ---------------- sequential greedy NMS on bitmask, single warp ----------------
__global__ void k_nms() {
  const int lane = threadIdx.x;  // 32 threads
  unsigned kw = 0;
  const unsigned validw = g_validmask[lane];
  const int CH = 8;
  unsigned buf[CH], nbuf[CH];
#pragma unroll
  for (int q = 0; q < CH; ++q) buf[q] = g_sup[q * 32 + lane];
  for (int c = 0; c < 1024 / CH; ++c) {
    if (c + 1 < 1024 / CH) {
#pragma unroll
      for (int q = 0; q < CH; ++q)
        nbuf[q] = g_sup[((c + 1) * CH + q) * 32 + lane];
    }
#pragma unroll
    for (int q = 0; q < CH; ++q) {
      int i = c * CH + q;
      bool sup = __any_sync(0xffffffffu, (buf[q] & kw) != 0u);
      unsigned vbit =
          (__shfl_sync(0xffffffffu, validw, i >> 5) >> (i & 31)) & 1u;
      if (!sup && vbit && lane == (i >> 5)) kw |= (1u << (i & 31));
    }
#pragma unroll
    for (int q = 0; q < CH; ++q) buf[q] = nbuf[q];
  }
  g_keepmask[lane] = kw;
}

// ---------------- masked gather to output ----------------
// layout (float32): boxes[1024*4] | labels[1024] | scores[1024] | confs[1024*21]
__global__ void k_out(float* __restrict__ out) {
  const int p = blockIdx.x * 256 + threadIdx.x;  // 0..1023
  const bool keep = (g_keepmask[p >> 5] >> (p & 31)) & 1u;
  const int idx = g_order[p];
  float4 b = g_sbox[p];
  out[p * 4 + 0] = keep ? b.x : -1.0f;
  out[p * 4 + 1] = keep ? b.y : -1.0f;
  out[p * 4 + 2] = keep ? b.z : -1.0f;
  out[p * 4 + 3] = keep ? b.w : -1.0f;
  out[4096 + p] = keep ? (float)g_labels[idx] : 0.0f;
  out[5120 + p] = keep ? g_sscore[p] : -1.0f;
  for (int c = 0; c < NCLS; ++c)
    out[6144 + p * NCLS + c] = keep ? g_confs[idx * NCLS + c] : -1.0f;
}

// ---------------- launch ----------------
extern "C" void kernel_launch(void* const* d_in, const int* in_sizes, int n_in,
                              void* d_out, int out_size) {
  const float* x = (const float*)d_in[0];
  const float* bb_w1 = (const float*)d_in[1];
  const float* bb_b1 = (const float*)d_in[2];
  const float* bb_w2 = (const float*)d_in[3];
  const float* bb_b2 = (const float*)d_in[4];
  const float* bb_w3 = (const float*)d_in[5];
  const float* bb_b3 = (const float*)d_in[6];
  const float* ex_w = (const float*)d_in[7];
  const float* ex_b = (const float*)d_in[8];
  const float* reg_w = (const float*)d_in[9];
  const float* reg_b = (const float*)d_in[10];
  const float* cls_w = (const float*)d_in[11];
  const float* cls_b = (const float*)d_in[12];

  // only batch element 7 affects the output
  const float* x7 = x + (size_t)7 * 3 * 512 * 512;

  k_conv1<<<dim3(16, 16, 16), 256>>>(x7, bb_w1, bb_b1);
  k_conv2<<<dim3(8, 8, 16), 256>>>(bb_w2, bb_b2);
  k_conv3<<<dim3(4, 4, 32), 256>>>(bb_w3, bb_b3);
  k_ex<<<dim3(2, 2, 32), 256>>>(ex_w, ex_b);
  k_head<<<dim3(8, 25), 256>>>(reg_w, cls_w);
  k_prep<<<4, 256>>>(reg_b, cls_b);
  k_sort<<<1, 1024>>>();
  k_iou<<<1024, 1024>>>();
  k_nms<<<1, 32>>>();
  k_out<<<4, 256>>>((float*)d_out);
}

// round 5
// speedup vs baseline: 1.8646x; 1.0646x over previous
#include <cuda_runtime.h>
#include <math.h>

#define NCLS 21

// ---------------- scratch (static device globals; no allocation) ----------------
__device__ float g_h1[64 * 256 * 256];    // conv1 out
__device__ float g_h2[128 * 128 * 128];   // conv2 out
__device__ float g_h3[256 * 64 * 64];     // conv3 out
__device__ float g_h4[256 * 32 * 32];     // ex out
__device__ float g_c3part[2 * 256 * 64 * 64];  // conv3 split-C partials
__device__ float g_expart[4 * 256 * 32 * 32];  // ex split-C partials
__device__ float g_part[8 * 25 * 1024];   // head conv split-K partials
__device__ float g_locs[1024 * 4];
__device__ float g_confs[1024 * NCLS];
__device__ float g_scores[1024];
__device__ int g_labels[1024];
__device__ int g_order[1024];
__device__ float4 g_sbox[1024];
__device__ float g_sscore[1024];
__device__ unsigned g_validmask[32];
__device__ unsigned g_sup[1024 * 32];
__device__ unsigned g_keepmask[32];

// ---------------- 3x3 conv, stride 2, SAME padding ----------------
// JAX SAME, even input, stride 2: pad_lo=0, pad_hi=1 (out = in/2).
// 16x16 output tile, COUTS output channels per block, 256 threads.
// NCH input channels staged per sync-pair; next group's loads prefetched into
// registers (fully unrolled -> high MLP) while current group computes.
// Numerics: per input channel, 9-term FMA chain (wsum), Kahan fold into acc
// (identical to the R2/R4-passing kernels). When FINAL=false the raw Kahan
// partial is stored (split-C); partials are combined in fp64 downstream.
template <int CIN, int WCH, int NCH, int STRIDE, int COUTS, int NCHUNK,
          bool FINAL>
__device__ __forceinline__ void conv_body(const float* __restrict__ in,
                                          const float* __restrict__ wgt,
                                          const float* __restrict__ bias,
                                          float* __restrict__ out, int Hin,
                                          int Win, int Hout, int Wout,
                                          int c_begin, int co0) {
  constexpr int TILE = 16;
  constexpr int IN_T = TILE * STRIDE + 2;
  constexpr int ROWP = IN_T + 2;
  constexpr int ELEMS = NCH * IN_T * IN_T;
  constexpr int LD = (ELEMS + 255) / 256;
  constexpr int G = WCH / NCH;
  constexpr int NW = WCH * 9 * COUTS;
  constexpr int WLD = (NW + 255) / 256;

  __shared__ float s_in[NCH * IN_T * ROWP];
  __shared__ __align__(16) float s_w[NW];

  const int t = threadIdx.x;
  const int tx = t & 15, ty = t >> 4;
  const int ow0 = blockIdx.x * TILE, oh0 = blockIdx.y * TILE;
  const int HW = Hin * Win;

  // per-thread load descriptors (same for every channel group)
  int goff[LD], soff[LD];
#pragma unroll
  for (int i = 0; i < LD; ++i) {
    int idx = t + i * 256;
    int ch = idx / (IN_T * IN_T);
    int rem = idx - ch * (IN_T * IN_T);
    int r = rem / IN_T, c = rem - r * IN_T;
    int ih = oh0 * STRIDE + r, iw = ow0 * STRIDE + c;
    bool ok = (idx < ELEMS) && ((unsigned)ih < (unsigned)Hin) &&
              ((unsigned)iw < (unsigned)Win);
    goff[i] = ok ? (ch * HW + ih * Win + iw) : -1;
    soff[i] = (ch * IN_T + r) * ROWP + c;
  }

  float acc[COUTS], cmp[COUTS];
#pragma unroll
  for (int i = 0; i < COUTS; i++) { acc[i] = 0.f; cmp[i] = 0.f; }

  for (int c0 = c_begin; c0 < c_begin + NCHUNK * WCH; c0 += WCH) {
    __syncthreads();  // previous chunk compute done; smem reusable
    // stage weight chunk: s_w[(ccg*9+k)*COUTS + co]
#pragma unroll
    for (int i = 0; i < WLD; ++i) {
      int idx = t + i * 256;
      if (idx < NW) {
        int co = idx / (WCH * 9);
        int rem = idx - co * (WCH * 9);
        int ccg = rem / 9, k = rem - ccg * 9;
        s_w[(ccg * 9 + k) * COUTS + co] =
            wgt[(size_t)(co0 + co) * CIN * 9 + (size_t)(c0 + ccg) * 9 + k];
      }
    }
    // prefetch group 0
    float rbuf[LD];
    {
      const float* inb = in + (size_t)c0 * HW;
#pragma unroll
      for (int i = 0; i < LD; ++i)
        rbuf[i] = (goff[i] >= 0) ? inb[goff[i]] : 0.f;
    }
    for (int g = 0; g < G; ++g) {
      __syncthreads();  // compute(g-1) done before overwriting s_in
#pragma unroll
      for (int i = 0; i < LD; ++i)
        if (t + i * 256 < ELEMS) s_in[soff[i]] = rbuf[i];
      if (g + 1 < G) {  // prefetch next group (overlaps with compute below)
        const float* inb = in + (size_t)(c0 + (g + 1) * NCH) * HW;
#pragma unroll
        for (int i = 0; i < LD; ++i)
          rbuf[i] = (goff[i] >= 0) ? inb[goff[i]] : 0.f;
      }
      __syncthreads();  // staging (weights + input) visible

#pragma unroll
      for (int cc = 0; cc < NCH; ++cc) {
        float wsum[COUTS];
#pragma unroll
        for (int i = 0; i < COUTS; ++i) wsum[i] = 0.f;
#pragma unroll
        for (int kh = 0; kh < 3; ++kh)
#pragma unroll
          for (int kw = 0; kw < 3; ++kw) {
            float xv = s_in[(cc * IN_T + ty * STRIDE + kh) * ROWP +
                            tx * STRIDE + kw];
            const float4* wp = (const float4*)&s_w[((g * NCH + cc) * 9 +
                                                    kh * 3 + kw) * COUTS];
#pragma unroll
            for (int q = 0; q < COUTS / 4; ++q) {
              float4 w4 = wp[q];
              wsum[q * 4 + 0] = fmaf(xv, w4.x, wsum[q * 4 + 0]);
              wsum[q * 4 + 1] = fmaf(xv, w4.y, wsum[q * 4 + 1]);
              wsum[q * 4 + 2] = fmaf(xv, w4.z, wsum[q * 4 + 2]);
              wsum[q * 4 + 3] = fmaf(xv, w4.w, wsum[q * 4 + 3]);
            }
          }
        // Kahan fold per channel
#pragma unroll
        for (int i = 0; i < COUTS; ++i) {
          float y = wsum[i] - cmp[i];
          float tt = acc[i] + y;
          cmp[i] = (tt - acc[i]) - y;
          acc[i] = tt;
        }
      }
    }
  }

  const int oh = oh0 + ty, ow = ow0 + tx;
#pragma unroll
  for (int i = 0; i < COUTS; i++) {
    float v = acc[i];
    if (FINAL) {
      v = v + bias[co0 + i];
      v = fmaxf(v, 0.f);
    }
    out[(size_t)(co0 + i) * Hout * Wout + (size_t)oh * Wout + ow] = v;
  }
}

__global__ void __launch_bounds__(256) k_conv1(const float* x, const float* w,
                                               const float* b) {
  conv_body<3, 3, 3, 2, 4, 1, true>(x, w, b, g_h1, 512, 512, 256, 256, 0,
                                    blockIdx.z * 4);
}
__global__ void __launch_bounds__(256) k_conv2(const float* w, const float* b) {
  conv_body<64, 64, 4, 2, 8, 1, true>(g_h1, w, b, g_h2, 256, 256, 128, 128, 0,
                                      blockIdx.z * 8);
}
// conv3: split-C x2. z = split*32 + co_blk.
__global__ void __launch_bounds__(256) k_conv3(const float* w) {
  const int split = blockIdx.z >> 5;
  const int co0 = (blockIdx.z & 31) * 8;
  conv_body<128, 64, 4, 2, 8, 1, false>(
      g_h2, w, nullptr, g_c3part + (size_t)split * 256 * 64 * 64, 128, 128, 64,
      64, split * 64, co0);
}
__global__ void k_comb3(const float* __restrict__ b) {
  const int i = blockIdx.x * 256 + threadIdx.x;  // 0 .. 256*64*64-1
  const int co = i >> 12;
  double s = (double)g_c3part[i] + (double)g_c3part[256 * 64 * 64 + i];
  float v = (float)(s + (double)b[co]);
  g_h3[i] = fmaxf(v, 0.f);
}
// ex: split-C x4. z = split*32 + co_blk.
__global__ void __launch_bounds__(256) k_ex(const float* w) {
  const int split = blockIdx.z >> 5;
  const int co0 = (blockIdx.z & 31) * 8;
  conv_body<256, 64, 4, 2, 8, 1, false>(
      g_h3, w, nullptr, g_expart + (size_t)split * 256 * 32 * 32, 64, 64, 32,
      32, split * 64, co0);
}
__global__ void k_combex(const float* __restrict__ b) {
  const int i = blockIdx.x * 256 + threadIdx.x;  // 0 .. 256*32*32-1
  const int co = i >> 10;
  double s = 0.0;
#pragma unroll
  for (int sp = 0; sp < 4; ++sp)
    s += (double)g_expart[(size_t)sp * 256 * 32 * 32 + i];
  float v = (float)(s + (double)b[co]);
  g_h4[i] = fmaxf(v, 0.f);
}

// ---------------- head convs (reg 4ch + cls 21ch), stride1 pad1, split-K -------
// grid: (split 0..7, cout 0..24). Block: 32 input channels, all 1024 px.
__global__ void __launch_bounds__(256) k_head(const float* __restrict__ reg_w,
                                              const float* __restrict__ cls_w) {
  constexpr int IN_T = 34, ROWP = 35, NCH = 4;
  constexpr int ELEMS = NCH * IN_T * IN_T;
  constexpr int LD = (ELEMS + 255) / 256;
  const int split = blockIdx.x, co = blockIdx.y;
  const float* w = (co < 4) ? (reg_w + (size_t)co * 256 * 9)
                            : (cls_w + (size_t)(co - 4) * 256 * 9);
  __shared__ float s_in[NCH * IN_T * ROWP];
  __shared__ float s_w[32 * 9];
  const int t = threadIdx.x;

  int goff[LD], soff[LD];
#pragma unroll
  for (int i = 0; i < LD; ++i) {
    int idx = t + i * 256;
    int ch = idx / (IN_T * IN_T);
    int rem = idx - ch * (IN_T * IN_T);
    int r = rem / IN_T, c = rem - r * IN_T;
    int ih = r - 1, iw = c - 1;
    bool ok = (idx < ELEMS) && ((unsigned)ih < 32u) && ((unsigned)iw < 32u);
    goff[i] = ok ? (ch * 1024 + ih * 32 + iw) : -1;
    soff[i] = (ch * IN_T + r) * ROWP + c;
  }
  for (int idx = t; idx < 32 * 9; idx += 256)
    s_w[idx] = w[(size_t)(split * 32 + idx / 9) * 9 + (idx % 9)];

  float acc[4] = {0.f, 0.f, 0.f, 0.f};
  float cmp[4] = {0.f, 0.f, 0.f, 0.f};

  float rbuf[LD];
  {
    const float* inb = g_h4 + (size_t)split * 32 * 1024;
#pragma unroll
    for (int i = 0; i < LD; ++i) rbuf[i] = (goff[i] >= 0) ? inb[goff[i]] : 0.f;
  }
  for (int g = 0; g < 8; ++g) {
    __syncthreads();
#pragma unroll
    for (int i = 0; i < LD; ++i)
      if (t + i * 256 < ELEMS) s_in[soff[i]] = rbuf[i];
    if (g + 1 < 8) {
      const float* inb = g_h4 + (size_t)(split * 32 + (g + 1) * NCH) * 1024;
#pragma unroll
      for (int i = 0; i < LD; ++i)
        rbuf[i] = (goff[i] >= 0) ? inb[goff[i]] : 0.f;
    }
    __syncthreads();

#pragma unroll
    for (int cc = 0; cc < NCH; ++cc) {
      float wr[9];
#pragma unroll
      for (int k = 0; k < 9; ++k) wr[k] = s_w[(g * NCH + cc) * 9 + k];
#pragma unroll
      for (int px = 0; px < 4; ++px) {
        int p = t + px * 256;
        int oh = p >> 5, ow = p & 31;
        float a = 0.f;
#pragma unroll
        for (int kh = 0; kh < 3; ++kh)
#pragma unroll
          for (int kw = 0; kw < 3; ++kw)
            a = fmaf(s_in[(cc * IN_T + oh + kh) * ROWP + ow + kw],
                     wr[kh * 3 + kw], a);
        float y = a - cmp[px];
        float tt = acc[px] + y;
        cmp[px] = (tt - acc[px]) - y;
        acc[px] = tt;
      }
    }
  }
#pragma unroll
  for (int px = 0; px < 4; ++px)
    g_part[(size_t)(split * 25 + co) * 1024 + t + px * 256] = acc[px];
}

// ---------------- reduce partials (double) + transpose + softmax (double) ------
__global__ void k_prep(const float* __restrict__ reg_b,
                       const float* __restrict__ cls_b) {
  const int a = blockIdx.x * 256 + threadIdx.x;  // anchor 0..1023
#pragma unroll
  for (int j = 0; j < 4; ++j) {
    double s = 0.0;
    for (int sp = 0; sp < 8; ++sp)
      s += (double)g_part[(size_t)(sp * 25 + j) * 1024 + a];
    g_locs[a * 4 + j] = (float)(s + (double)reg_b[j]);
  }
  float conf[NCLS];
  for (int c = 0; c < NCLS; ++c) {
    double s = 0.0;
    for (int sp = 0; sp < 8; ++sp)
      s += (double)g_part[(size_t)(sp * 25 + 4 + c) * 1024 + a];
    conf[c] = (float)(s + (double)cls_b[c]);
    g_confs[a * NCLS + c] = conf[c];
  }
  float m = conf[0];
  int lab = 0;
  for (int c = 1; c < NCLS; ++c)
    if (conf[c] > m) { m = conf[c]; lab = c; }
  double sum = 0.0;
  for (int c = 0; c < NCLS; ++c) sum += exp((double)conf[c] - (double)m);
  g_scores[a] = (float)(1.0 / sum);  // max softmax prob
  g_labels[a] = lab;
}

// ---------------- stable bitonic sort by descending score ----------------
__global__ void k_sort() {
  __shared__ float s[1024];
  __shared__ int si[1024];
  const int t = threadIdx.x;
  s[t] = g_scores[t];
  si[t] = t;
  __syncthreads();
  for (int k = 2; k <= 1024; k <<= 1) {
    for (int j = k >> 1; j > 0; j >>= 1) {
      int ixj = t ^ j;
      if (ixj > t) {
        float sa = s[t], sb = s[ixj];
        int ia = si[t], ib = si[ixj];
        bool aFirst = (sa > sb) || (sa == sb && ia < ib);  // stable desc
        bool dirUp = ((t & k) == 0);
        if (dirUp ? !aFirst : aFirst) {
          s[t] = sb; s[ixj] = sa;
          si[t] = ib; si[ixj] = ia;
        }
      }
      __syncthreads();
    }
  }
  const int idx = si[t];
  g_order[t] = idx;
  g_sscore[t] = s[t];
  g_sbox[t] = make_float4(g_locs[idx * 4 + 0], g_locs[idx * 4 + 1],
                          g_locs[idx * 4 + 2], g_locs[idx * 4 + 3]);
  unsigned vb = __ballot_sync(0xffffffffu, s[t] > 0.04f);
  if ((t & 31) == 0) g_validmask[t >> 5] = vb;
}

// ---------------- pairwise IoU suppression bitmask (double precision) ----------
__global__ void k_iou() {
  const int i = blockIdx.x, j = threadIdx.x;
  float4 bi = g_sbox[i];
  float4 bj = g_sbox[j];
  double ai = ((double)bi.z - (double)bi.x) * ((double)bi.w - (double)bi.y);
  double aj = ((double)bj.z - (double)bj.x) * ((double)bj.w - (double)bj.y);
  double ltx = fmax((double)bi.x, (double)bj.x);
  double lty = fmax((double)bi.y, (double)bj.y);
  double rbx = fmin((double)bi.z, (double)bj.z);
  double rby = fmin((double)bi.w, (double)bj.w);
  double inter = fmax(rbx - ltx, 0.0) * fmax(rby - lty, 0.0);
  double uni = ai + aj - inter;
  double iou = inter / (uni + 1e-9);
  unsigned m = __ballot_sync(0xffffffffu, iou > 0.5);
  if ((j & 31) == 0) g_sup[i * 32 + (j >> 5)] = m;
}

// ---------------- sequential greedy NMS on bitmask, single warp ----------------
__global__ void k_nms() {
  const int lane = threadIdx.x;  // 32 threads
  unsigned kw = 0;
  const unsigned validw = g_validmask[lane];
  const int CH = 8;
  unsigned buf[CH], nbuf[CH];
#pragma unroll
  for (int q = 0; q < CH; ++q) buf[q] = g_sup[q * 32 + lane];
  for (int c = 0; c < 1024 / CH; ++c) {
    if (c + 1 < 1024 / CH) {
#pragma unroll
      for (int q = 0; q < CH; ++q)
        nbuf[q] = g_sup[((c + 1) * CH + q) * 32 + lane];
    }
#pragma unroll
    for (int q = 0; q < CH; ++q) {
      int i = c * CH + q;
      bool sup = __any_sync(0xffffffffu, (buf[q] & kw) != 0u);
      unsigned vbit =
          (__shfl_sync(0xffffffffu, validw, i >> 5) >> (i & 31)) & 1u;
      if (!sup && vbit && lane == (i >> 5)) kw |= (1u << (i & 31));
    }
#pragma unroll
    for (int q = 0; q < CH; ++q) buf[q] = nbuf[q];
  }
  g_keepmask[lane] = kw;
}

// ---------------- masked gather to output ----------------
// layout (float32): boxes[1024*4] | labels[1024] | scores[1024] | confs[1024*21]
__global__ void k_out(float* __restrict__ out) {
  const int p = blockIdx.x * 256 + threadIdx.x;  // 0..1023
  const bool keep = (g_keepmask[p >> 5] >> (p & 31)) & 1u;
  const int idx = g_order[p];
  float4 b = g_sbox[p];
  out[p * 4 + 0] = keep ? b.x : -1.0f;
  out[p * 4 + 1] = keep ? b.y : -1.0f;
  out[p * 4 + 2] = keep ? b.z : -1.0f;
  out[p * 4 + 3] = keep ? b.w : -1.0f;
  out[4096 + p] = keep ? (float)g_labels[idx] : 0.0f;
  out[5120 + p] = keep ? g_sscore[p] : -1.0f;
  for (int c = 0; c < NCLS; ++c)
    out[6144 + p * NCLS + c] = keep ? g_confs[idx * NCLS + c] : -1.0f;
}

// ---------------- launch ----------------
extern "C" void kernel_launch(void* const* d_in, const int* in_sizes, int n_in,
                              void* d_out, int out_size) {
  const float* x = (const float*)d_in[0];
  const float* bb_w1 = (const float*)d_in[1];
  const float* bb_b1 = (const float*)d_in[2];
  const float* bb_w2 = (const float*)d_in[3];
  const float* bb_b2 = (const float*)d_in[4];
  const float* bb_w3 = (const float*)d_in[5];
  const float* bb_b3 = (const float*)d_in[6];
  const float* ex_w = (const float*)d_in[7];
  const float* ex_b = (const float*)d_in[8];
  const float* reg_w = (const float*)d_in[9];
  const float* reg_b = (const float*)d_in[10];
  const float* cls_w = (const float*)d_in[11];
  const float* cls_b = (const float*)d_in[12];

  // only batch element 7 affects the output
  const float* x7 = x + (size_t)7 * 3 * 512 * 512;

  k_conv1<<<dim3(16, 16, 16), 256>>>(x7, bb_w1, bb_b1);
  k_conv2<<<dim3(8, 8, 16), 256>>>(bb_w2, bb_b2);
  k_conv3<<<dim3(4, 4, 64), 256>>>(bb_w3);
  k_comb3<<<4096, 256>>>(bb_b3);
  k_ex<<<dim3(2, 2, 128), 256>>>(ex_w);
  k_combex<<<1024, 256>>>(ex_b);
  k_head<<<dim3(8, 25), 256>>>(reg_w, cls_w);
  k_prep<<<4, 256>>>(reg_b, cls_b);
  k_sort<<<1, 1024>>>();
  k_iou<<<1024, 1024>>>();
  k_nms<<<1, 32>>>();
  k_out<<<4, 256>>>((float*)d_out);
}